// round 8
// baseline (speedup 1.0000x reference)
#include <cuda_runtime.h>

// ---------------------------------------------------------------------------
// GAT collapses (uniform per-item node features; per-dst softmax weights sum
// to 1 via self-loops) => whole model = 7-layer MLP on 64 batch rows.
// 32 blocks x 512 threads; block bx owns rows {2bx, 2bx+1}.
// Weights flow gmem->smem via a cp.async 3-buffer ring of 64KB chunks that
// runs continuously across layers (copies never block on activations).
// Thread = (output o, K-half kh); each weight byte enters the SM exactly once.
// Packed k4-interleaved weight layout -> conflict-free LDS + coalesced copy.
// ---------------------------------------------------------------------------

typedef unsigned long long ULL;
typedef unsigned int U32;

__device__ __forceinline__ void ffma2(ULL& d, ULL a, ULL b) {
    asm("fma.rn.f32x2 %0, %1, %2, %0;" : "+l"(d) : "l"(a), "l"(b));
}
__device__ __forceinline__ void fadd2(ULL& d, ULL a) {
    asm("add.rn.f32x2 %0, %1, %0;" : "+l"(d) : "l"(a));
}
__device__ __forceinline__ float2 unpack2f(ULL v) {
    float2 f; asm("mov.b64 {%0, %1}, %2;" : "=f"(f.x), "=f"(f.y) : "l"(v)); return f;
}

// ---- packed weights: float4 idx (within region) = k4*O + o ----------------
// Region offsets in QUADS (float4 units).
#define Q_IN   0        // W_in   256x64   (Kq=16)
#define Q_G0   4096     // gat_W0 256x256  (Kq=64)
#define Q_G1   20480
#define Q_G2   36864
#define Q_F    53248    // W_fuse 256x320  (Kq=80)
#define Q_S1   73728    // [p1;d1] 256x256
#define Q_P2   90112    // W_p2   64x128   (Kq=32)
#define Q_D2   92160
#define Q_TOTAL 94208

__device__ __align__(16) float4 g_packed[Q_TOTAL];

__global__ void pack_kernel(const float4* __restrict__ W_in,
                            const float4* __restrict__ gat_W,
                            const float4* __restrict__ W_fuse,
                            const float4* __restrict__ W_p1,
                            const float4* __restrict__ W_d1,
                            const float4* __restrict__ W_p2,
                            const float4* __restrict__ W_d2) {
    int stride = gridDim.x * blockDim.x;
    for (int e = blockIdx.x * blockDim.x + threadIdx.x; e < Q_TOTAL; e += stride) {
        const float4* src; int le, Kq, Ocomb, obase, offq;
        if (e < 4096)       { src = W_in;          le = e;         Kq = 16; Ocomb = 256; obase = 0;   offq = Q_IN; }
        else if (e < 20480) { src = gat_W;         le = e - 4096;  Kq = 64; Ocomb = 256; obase = 0;   offq = Q_G0; }
        else if (e < 36864) { src = gat_W + 16384; le = e - 20480; Kq = 64; Ocomb = 256; obase = 0;   offq = Q_G1; }
        else if (e < 53248) { src = gat_W + 32768; le = e - 36864; Kq = 64; Ocomb = 256; obase = 0;   offq = Q_G2; }
        else if (e < 73728) { src = W_fuse;        le = e - 53248; Kq = 80; Ocomb = 256; obase = 0;   offq = Q_F;  }
        else if (e < 81920) { src = W_p1;          le = e - 73728; Kq = 64; Ocomb = 256; obase = 0;   offq = Q_S1; }
        else if (e < 90112) { src = W_d1;          le = e - 81920; Kq = 64; Ocomb = 256; obase = 128; offq = Q_S1; }
        else if (e < 92160) { src = W_p2;          le = e - 90112; Kq = 32; Ocomb = 64;  obase = 0;   offq = Q_P2; }
        else                { src = W_d2;          le = e - 92160; Kq = 32; Ocomb = 64;  obase = 0;   offq = Q_D2; }
        int o  = le / Kq;
        int k4 = le - o * Kq;
        g_packed[offq + k4 * Ocomb + obase + o] = src[o * Kq + k4];
    }
}

// ---- cp.async machinery ----------------------------------------------------
#define NCHUNK 23
#define CQ 4096                      // quads per 64KB chunk

__device__ __forceinline__ void issue_chunk(int c, float4* sdst, int t) {
    const float4* g = g_packed + (size_t)c * CQ;
    #pragma unroll
    for (int j = 0; j < 8; j++) {
        U32 sa = (U32)__cvta_generic_to_shared(sdst + j * 512 + t);
        asm volatile("cp.async.cg.shared.global [%0], [%1], 16;"
                     :: "r"(sa), "l"(g + j * 512 + t) : "memory");
    }
    asm volatile("cp.async.commit_group;" ::: "memory");
}
__device__ __forceinline__ void wait_g(int a) {
    if (a >= 2)      asm volatile("cp.async.wait_group 2;" ::: "memory");
    else if (a == 1) asm volatile("cp.async.wait_group 1;" ::: "memory");
    else             asm volatile("cp.async.wait_group 0;" ::: "memory");
}

__global__ __launch_bounds__(512, 1) void net_kernel(
    const float* __restrict__ x, const int* __restrict__ cidx,
    const float* __restrict__ b_in, const float* __restrict__ gat_b,
    const float* __restrict__ emb, const float* __restrict__ b_fuse,
    const float* __restrict__ b_p1, const float* __restrict__ b_d1,
    const float* __restrict__ b_p2, const float* __restrict__ b_d2,
    const float* __restrict__ W_p3, const float* __restrict__ b_p3,
    const float* __restrict__ W_d3, const float* __restrict__ b_d3,
    float* __restrict__ out) {

    extern __shared__ __align__(16) float4 ring[];     // 3 * CQ quads (192KB)

    __shared__ __align__(16) float  X0[64], X1[64];
    __shared__ __align__(16) float  A0[336], A1[336], B0[336], B1[336];
    __shared__ __align__(16) float2 P[2][256];
    __shared__ __align__(16) float  C0[128], C1[128];

    const int t  = threadIdx.x;
    const int bx = blockIdx.x;
    const int o  = t & 255;     // output feature
    const int kh = t >> 8;      // K half

    int issued = 0, cons = 0;
    #define ISSUE() do { if (issued < NCHUNK) { \
        issue_chunk(issued, ring + (issued % 3) * CQ, t); issued++; } } while (0)
    #define WAITSYNC() do { wait_g(NCHUNK - 1 - cons); __syncthreads(); } while (0)

    ISSUE(); ISSUE(); ISSUE();

    // ---- stage inputs: x rows; emb[cidx] -> B[256..319] (fuse tail) ----
    if (t < 32) {
        int r = t >> 4, q = t & 15;
        float4 v = ((const float4*)x)[(2 * bx + r) * 16 + q];
        ((float4*)(r ? X1 : X0))[q] = v;
    } else if (t < 64) {
        int i = t - 32, r = i >> 4, q = i & 15;
        int ci = cidx[2 * bx + r];
        float4 v = ((const float4*)emb)[ci * 16 + q];
        ((float4*)((r ? B1 : B0) + 256))[q] = v;
    }

    // Big layer: NC chunks; acts IN0/IN1, outputs OUT0/OUT1, bias expr uses t.
    #define BIGLAYER(NC, IN0, IN1, OUT0, OUT1, BIASEXPR)                     \
    {                                                                        \
        ULL p0 = 0ull, q0 = 0ull, p1 = 0ull, q1 = 0ull;                      \
        for (int lc = 0; lc < (NC); lc++) {                                  \
            WAITSYNC();                                                      \
            const longlong2* wb = (const longlong2*)(ring + (cons % 3) * CQ);\
            const longlong2* a0 = (const longlong2*)IN0 + lc * 16 + kh * 8;  \
            const longlong2* a1 = (const longlong2*)IN1 + lc * 16 + kh * 8;  \
            _Pragma("unroll")                                                \
            for (int i = 0; i < 8; i++) {                                    \
                longlong2 w  = wb[(kh * 8 + i) * 256 + o];                   \
                longlong2 x0 = a0[i];                                        \
                longlong2 x1 = a1[i];                                        \
                ffma2(p0, (ULL)w.x, (ULL)x0.x);                              \
                ffma2(q0, (ULL)w.y, (ULL)x0.y);                              \
                ffma2(p1, (ULL)w.x, (ULL)x1.x);                              \
                ffma2(q1, (ULL)w.y, (ULL)x1.y);                              \
            }                                                                \
            cons++;                                                          \
            if (lc == (NC) - 1) {                                            \
                fadd2(p0, q0); fadd2(p1, q1);                                \
                float2 f0 = unpack2f(p0), f1 = unpack2f(p1);                 \
                P[kh][o] = make_float2(f0.x + f0.y, f1.x + f1.y);            \
            }                                                                \
            __syncthreads();                                                 \
            ISSUE();                                                         \
        }                                                                    \
        if (t < 256) {                                                       \
            float2 u = P[0][t], v = P[1][t];                                 \
            float bb = (BIASEXPR);                                           \
            OUT0[t] = fmaxf(u.x + v.x + bb, 0.f);                            \
            OUT1[t] = fmaxf(u.y + v.y + bb, 0.f);                            \
        }                                                                    \
    }

    // L0: [256x64]  X -> A           (chunk 0)
    BIGLAYER(1, X0, X1, A0, A1, b_in[t]);
    // L1..L3: collapsed GAT [256x256] (chunks 1-12)
    BIGLAYER(4, A0, A1, B0, B1, gat_b[t]);
    BIGLAYER(4, B0, B1, A0, A1, gat_b[256 + t]);
    BIGLAYER(4, A0, A1, B0, B1, gat_b[512 + t]);
    // L4: fuse [256x320] over [g3 ; emb] (chunks 13-17)
    BIGLAYER(5, B0, B1, A0, A1, b_fuse[t]);
    // L5: heads stage1 [p1 ; d1] = [256x256] (chunks 18-21)
    BIGLAYER(4, A0, A1, B0, B1, (t < 128) ? b_p1[t] : b_d1[t - 128]);

    // ---- L6: p2/d2 each [64x128], chunk 22 = [P2 ; D2] ----
    {
        WAITSYNC();
        const longlong2* wb = (const longlong2*)(ring + (cons % 3) * CQ);
        const int kq = t >> 7;          // K quarter
        const int o6 = t & 127;         // 0..63 p2, 64..127 d2
        const bool isd = (o6 >= 64);
        const int ol = isd ? (o6 - 64) : o6;
        const int wq = (isd ? 2048 : 0);
        const longlong2* a0 = (const longlong2*)B0 + (isd ? 32 : 0) + kq * 8;
        const longlong2* a1 = (const longlong2*)B1 + (isd ? 32 : 0) + kq * 8;
        ULL p0 = 0ull, q0 = 0ull, p1 = 0ull, q1 = 0ull;
        #pragma unroll
        for (int i = 0; i < 8; i++) {
            longlong2 w  = wb[wq + (kq * 8 + i) * 64 + ol];
            longlong2 x0 = a0[i];
            longlong2 x1 = a1[i];
            ffma2(p0, (ULL)w.x, (ULL)x0.x);
            ffma2(q0, (ULL)w.y, (ULL)x0.y);
            ffma2(p1, (ULL)w.x, (ULL)x1.x);
            ffma2(q1, (ULL)w.y, (ULL)x1.y);
        }
        cons++;
        fadd2(p0, q0); fadd2(p1, q1);
        float2 f0 = unpack2f(p0), f1 = unpack2f(p1);
        float2* P4 = &P[0][0];                      // reuse as [4][128]
        P4[kq * 128 + o6] = make_float2(f0.x + f0.y, f1.x + f1.y);
        __syncthreads();
        if (t < 128) {
            float2 s0 = P4[t], s1 = P4[128 + t], s2 = P4[256 + t], s3 = P4[384 + t];
            float b2 = (t < 64) ? b_p2[t] : b_d2[t - 64];
            C0[t] = fmaxf(s0.x + s1.x + s2.x + s3.x + b2, 0.f);
            C1[t] = fmaxf(s0.y + s1.y + s2.y + s3.y + b2, 0.f);
        }
    }
    __syncthreads();

    // ---- L7: final 64-dots; warps 0-3 = {r0 price, r0 dir, r1 price, r1 dir}
    const int w = t >> 5, lane = t & 31;
    if (w < 4) {
        const int r = w >> 1, isd = w & 1;
        const float* W3 = isd ? W_d3 : W_p3;
        const float* Cv = (r ? C1 : C0) + isd * 64;
        float v = W3[lane] * Cv[lane] + W3[lane + 32] * Cv[lane + 32];
        #pragma unroll
        for (int m = 16; m; m >>= 1)
            v += __shfl_xor_sync(0xffffffffu, v, m);
        if (lane == 0) {
            int rg = 2 * bx + r;
            if (!isd) out[rg] = v + b_p3[0];
            else      out[64 + rg] = 1.f / (1.f + __expf(-(v + b_d3[0])));
        }
    }
    #undef ISSUE
    #undef WAITSYNC
    #undef BIGLAYER
}

extern "C" void kernel_launch(void* const* d_in, const int* in_sizes, int n_in,
                              void* d_out, int out_size) {
    const float* x      = (const float*)d_in[0];
    const int*   cidx   = (const int*)  d_in[1];
    // d_in[2] edge_index, d_in[3] edge_attr: unused (softmax collapse)
    const float* W_in   = (const float*)d_in[4];
    const float* b_in   = (const float*)d_in[5];
    const float* gat_W  = (const float*)d_in[6];
    // d_in[7..10]: attention params — unused (collapse)
    const float* gat_b  = (const float*)d_in[11];
    const float* emb    = (const float*)d_in[12];
    const float* W_fuse = (const float*)d_in[13];
    const float* b_fuse = (const float*)d_in[14];
    const float* W_p1   = (const float*)d_in[15];
    const float* b_p1   = (const float*)d_in[16];
    const float* W_p2   = (const float*)d_in[17];
    const float* b_p2   = (const float*)d_in[18];
    const float* W_p3   = (const float*)d_in[19];
    const float* b_p3   = (const float*)d_in[20];
    const float* W_d1   = (const float*)d_in[21];
    const float* b_d1   = (const float*)d_in[22];
    const float* W_d2   = (const float*)d_in[23];
    const float* b_d2   = (const float*)d_in[24];
    const float* W_d3   = (const float*)d_in[25];
    const float* b_d3   = (const float*)d_in[26];

    const int ring_bytes = 3 * 4096 * 16;   // 192KB dynamic smem
    cudaFuncSetAttribute(net_kernel, cudaFuncAttributeMaxDynamicSharedMemorySize,
                         ring_bytes);

    pack_kernel<<<128, 256>>>((const float4*)W_in, (const float4*)gat_W,
                              (const float4*)W_fuse, (const float4*)W_p1,
                              (const float4*)W_d1, (const float4*)W_p2,
                              (const float4*)W_d2);
    net_kernel<<<32, 512, ring_bytes>>>(x, cidx, b_in, gat_b, emb, b_fuse,
                                        b_p1, b_d1, b_p2, b_d2,
                                        W_p3, b_p3, W_d3, b_d3, (float*)d_out);
}

// round 9
// speedup vs baseline: 1.3735x; 1.3735x over previous
#include <cuda_runtime.h>

// ---------------------------------------------------------------------------
// GAT collapses (uniform per-item node features; per-dst softmax weights sum
// to 1 via self-loops) => whole model = 7-layer MLP on 64 batch rows.
// 32 clusters x 2 CTAs x 512 thr. Cluster c owns rows {2c, 2c+1}; each CTA
// computes 128/256 outputs per layer (halves per-SM weight traffic), then
// stores results locally AND into the peer CTA's smem (one st.shared::cluster
// per value), one barrier.cluster per layer. Weights k4-interleaved (packed).
// ---------------------------------------------------------------------------

typedef unsigned long long ULL;
typedef unsigned int U32;

__device__ __forceinline__ void ffma2(ULL& d, ULL a, ULL b) {
    asm("fma.rn.f32x2 %0, %1, %2, %0;" : "+l"(d) : "l"(a), "l"(b));
}
__device__ __forceinline__ void fadd2(ULL& d, ULL a) {
    asm("add.rn.f32x2 %0, %1, %0;" : "+l"(d) : "l"(a));
}
__device__ __forceinline__ float2 unpack2f(ULL v) {
    float2 f; asm("mov.b64 {%0, %1}, %2;" : "=f"(f.x), "=f"(f.y) : "l"(v)); return f;
}
__device__ __forceinline__ U32 smem_u32(const void* p) {
    return (U32)__cvta_generic_to_shared(p);
}
#define CLUSTER_SYNC() do { \
    asm volatile("barrier.cluster.arrive.aligned;" ::: "memory"); \
    asm volatile("barrier.cluster.wait.aligned;"   ::: "memory"); \
} while (0)

// ---- packed weights: quad idx (in region) = k4*O + o ----------------------
#define Q_IN   0        // W_in   256x64   O=256 Kq=16
#define Q_G0   4096     // gat_W0 256x256  O=256 Kq=64
#define Q_G1   20480
#define Q_G2   36864
#define Q_F    53248    // W_fuse 256x320  O=256 Kq=80
#define Q_S1   73728    // [p1;d1] 256x256 O=256 Kq=64
#define Q_2    90112    // [p2;d2] 128x128 O=128 Kq=32
#define Q_TOTAL 94208

__device__ __align__(16) float4 g_packed[Q_TOTAL];

__global__ void pack_kernel(const float4* __restrict__ W_in,
                            const float4* __restrict__ gat_W,
                            const float4* __restrict__ W_fuse,
                            const float4* __restrict__ W_p1,
                            const float4* __restrict__ W_d1,
                            const float4* __restrict__ W_p2,
                            const float4* __restrict__ W_d2) {
    int stride = gridDim.x * blockDim.x;
    for (int e = blockIdx.x * blockDim.x + threadIdx.x; e < Q_TOTAL; e += stride) {
        const float4* src; int le, Kq, Ocomb, obase, offq;
        if (e < 4096)       { src = W_in;          le = e;         Kq = 16; Ocomb = 256; obase = 0;   offq = Q_IN; }
        else if (e < 20480) { src = gat_W;         le = e - 4096;  Kq = 64; Ocomb = 256; obase = 0;   offq = Q_G0; }
        else if (e < 36864) { src = gat_W + 16384; le = e - 20480; Kq = 64; Ocomb = 256; obase = 0;   offq = Q_G1; }
        else if (e < 53248) { src = gat_W + 32768; le = e - 36864; Kq = 64; Ocomb = 256; obase = 0;   offq = Q_G2; }
        else if (e < 73728) { src = W_fuse;        le = e - 53248; Kq = 80; Ocomb = 256; obase = 0;   offq = Q_F;  }
        else if (e < 81920) { src = W_p1;          le = e - 73728; Kq = 64; Ocomb = 256; obase = 0;   offq = Q_S1; }
        else if (e < 90112) { src = W_d1;          le = e - 81920; Kq = 64; Ocomb = 256; obase = 128; offq = Q_S1; }
        else if (e < 92160) { src = W_p2;          le = e - 90112; Kq = 32; Ocomb = 128; obase = 0;   offq = Q_2;  }
        else                { src = W_d2;          le = e - 92160; Kq = 32; Ocomb = 128; obase = 64;  offq = Q_2;  }
        int o  = le / Kq;
        int k4 = le - o * Kq;
        g_packed[offq + k4 * Ocomb + obase + o] = src[o * Kq + k4];
    }
}

__global__ __launch_bounds__(512, 1) __cluster_dims__(2, 1, 1)
void net_kernel(
    const float* __restrict__ x, const int* __restrict__ cidx,
    const float* __restrict__ b_in, const float* __restrict__ gat_b,
    const float* __restrict__ emb, const float* __restrict__ b_fuse,
    const float* __restrict__ b_p1, const float* __restrict__ b_d1,
    const float* __restrict__ b_p2, const float* __restrict__ b_d2,
    const float* __restrict__ W_p3, const float* __restrict__ b_p3,
    const float* __restrict__ W_d3, const float* __restrict__ b_d3,
    float* __restrict__ out) {

    __shared__ __align__(16) float  X0[64], X1[64];
    __shared__ __align__(16) float  A0[336], A1[336], B0[336], B1[336];
    __shared__ __align__(16) float2 P[4][128];
    __shared__ __align__(16) float  C[128];

    const int t  = threadIdx.x;
    const int o  = t & 127;     // output within CTA's half
    const int kq = t >> 7;      // K quarter 0..3
    U32 rank; asm("mov.u32 %0, %%cluster_ctarank;" : "=r"(rank));
    const int peer = (int)rank ^ 1;
    const int ot = (int)rank * 128 + (t & 127);  // this thread's combine output

    // Peer smem addresses for remote result stores.
    U32 pa0, pa1, pb0, pb1;
    {
        U32 la0 = smem_u32(A0), la1 = smem_u32(A1);
        U32 lb0 = smem_u32(B0), lb1 = smem_u32(B1);
        asm("mapa.shared::cluster.u32 %0, %1, %2;" : "=r"(pa0) : "r"(la0), "r"(peer));
        asm("mapa.shared::cluster.u32 %0, %1, %2;" : "=r"(pa1) : "r"(la1), "r"(peer));
        asm("mapa.shared::cluster.u32 %0, %1, %2;" : "=r"(pb0) : "r"(lb0), "r"(peer));
        asm("mapa.shared::cluster.u32 %0, %1, %2;" : "=r"(pb1) : "r"(lb1), "r"(peer));
    }

    const int row0 = blockIdx.x & ~1;            // cluster's first global row

    // ---- stage inputs locally: x rows -> X; emb[cidx] -> B[256..319] ----
    if (t < 32) {
        int r = t >> 4, q = t & 15;
        float4 v = ((const float4*)x)[(row0 + r) * 16 + q];
        ((float4*)(r ? X1 : X0))[q] = v;
    } else if (t < 64) {
        int i = t - 32, r = i >> 4, q = i & 15;
        int ci = cidx[row0 + r];
        float4 v = ((const float4*)emb)[ci * 16 + q];
        ((float4*)((r ? B1 : B0) + 256))[q] = v;
    }
    __syncthreads();

    // One layer: CTA computes outputs [rank*128, rank*128+128) over K=KQ4*16.
    #define LAYER(QBASE, KQ4, IN0, IN1, OUT0, OUT1, RADDR0, RADDR1, BIASEXPR) \
    {                                                                         \
        const longlong2* W  = (const longlong2*)g_packed +                    \
            (size_t)(QBASE) + (size_t)(kq * (KQ4)) * 256 + rank * 128 + o;    \
        const longlong2* Aq = (const longlong2*)IN0 + kq * (KQ4);             \
        const longlong2* Bq = (const longlong2*)IN1 + kq * (KQ4);             \
        ULL p0 = 0ull, q0 = 0ull, p1 = 0ull, q1 = 0ull;                       \
        _Pragma("unroll")                                                     \
        for (int i = 0; i < (KQ4); i++) {                                     \
            longlong2 w  = W[(size_t)i * 256];                                \
            longlong2 x0 = Aq[i];                                             \
            longlong2 x1 = Bq[i];                                             \
            ffma2(p0, (ULL)w.x, (ULL)x0.x);                                   \
            ffma2(q0, (ULL)w.y, (ULL)x0.y);                                   \
            ffma2(p1, (ULL)w.x, (ULL)x1.x);                                   \
            ffma2(q1, (ULL)w.y, (ULL)x1.y);                                   \
        }                                                                     \
        fadd2(p0, q0); fadd2(p1, q1);                                         \
        float2 f0 = unpack2f(p0), f1 = unpack2f(p1);                          \
        P[kq][o] = make_float2(f0.x + f0.y, f1.x + f1.y);                     \
        __syncthreads();                                                      \
        if (t < 128) {                                                        \
            float2 s0 = P[0][t], s1 = P[1][t], s2 = P[2][t], s3 = P[3][t];    \
            float bb = (BIASEXPR);                                            \
            float v0 = fmaxf(s0.x + s1.x + s2.x + s3.x + bb, 0.f);            \
            float v1 = fmaxf(s0.y + s1.y + s2.y + s3.y + bb, 0.f);            \
            OUT0[ot] = v0; OUT1[ot] = v1;                                     \
            asm volatile("st.shared::cluster.f32 [%0], %1;"                   \
                         :: "r"(RADDR0 + (U32)ot * 4u), "f"(v0) : "memory");  \
            asm volatile("st.shared::cluster.f32 [%0], %1;"                   \
                         :: "r"(RADDR1 + (U32)ot * 4u), "f"(v1) : "memory");  \
        }                                                                     \
        CLUSTER_SYNC();                                                       \
    }

    // L0: [256x64]  X -> A
    LAYER(Q_IN, 4,  X0, X1, A0, A1, pa0, pa1, b_in[ot]);
    // L1..L3: collapsed GAT [256x256]
    LAYER(Q_G0, 16, A0, A1, B0, B1, pb0, pb1, gat_b[ot]);
    LAYER(Q_G1, 16, B0, B1, A0, A1, pa0, pa1, gat_b[256 + ot]);
    LAYER(Q_G2, 16, A0, A1, B0, B1, pb0, pb1, gat_b[512 + ot]);
    // L4: fuse [256x320] over [g3 ; emb]  B -> A
    LAYER(Q_F,  20, B0, B1, A0, A1, pa0, pa1, b_fuse[ot]);
    // L5: heads stage1 [p1 ; d1] = [256x256]  A -> B
    LAYER(Q_S1, 16, A0, A1, B0, B1, pb0, pb1,
          (ot < 128) ? b_p1[ot] : b_d1[ot - 128]);
    #undef LAYER

    // ---- Tail (CTA-local): CTA handles global row (row0 + rank). ----
    // L6: [p2;d2] 128 outs, K=128 over this row's B acts.
    {
        const float* Brow = rank ? B1 : B0;
        const longlong2* W  = (const longlong2*)g_packed +
            (size_t)Q_2 + (size_t)(kq * 8) * 128 + o;
        const longlong2* Aq = (const longlong2*)Brow + ((o >= 64) ? 32 : 0) + kq * 8;
        ULL p0 = 0ull, q0 = 0ull;
        #pragma unroll
        for (int i = 0; i < 8; i++) {
            longlong2 w  = W[(size_t)i * 128];
            longlong2 x0 = Aq[i];
            ffma2(p0, (ULL)w.x, (ULL)x0.x);
            ffma2(q0, (ULL)w.y, (ULL)x0.y);
        }
        fadd2(p0, q0);
        float2 f0 = unpack2f(p0);
        P[kq][o].x = f0.x + f0.y;
        __syncthreads();
        if (t < 128) {
            float b2 = (t < 64) ? b_p2[t] : b_d2[t - 64];
            C[t] = fmaxf(P[0][t].x + P[1][t].x + P[2][t].x + P[3][t].x + b2, 0.f);
        }
        __syncthreads();
    }

    // L7: price (warp 0) / direction (warp 1) for row (row0 + rank).
    {
        const int w = t >> 5, lane = t & 31;
        if (w < 2) {
            const float* W3 = w ? W_d3 : W_p3;
            const float* Cv = C + w * 64;
            float v = W3[lane] * Cv[lane] + W3[lane + 32] * Cv[lane + 32];
            #pragma unroll
            for (int m = 16; m; m >>= 1)
                v += __shfl_xor_sync(0xffffffffu, v, m);
            if (lane == 0) {
                int rg = row0 + (int)rank;
                if (!w) out[rg] = v + b_p3[0];
                else    out[64 + rg] = 1.f / (1.f + __expf(-(v + b_d3[0])));
            }
        }
    }
}

extern "C" void kernel_launch(void* const* d_in, const int* in_sizes, int n_in,
                              void* d_out, int out_size) {
    const float* x      = (const float*)d_in[0];
    const int*   cidx   = (const int*)  d_in[1];
    // d_in[2] edge_index, d_in[3] edge_attr: unused (softmax collapse)
    const float* W_in   = (const float*)d_in[4];
    const float* b_in   = (const float*)d_in[5];
    const float* gat_W  = (const float*)d_in[6];
    // d_in[7..10]: attention params — unused (collapse)
    const float* gat_b  = (const float*)d_in[11];
    const float* emb    = (const float*)d_in[12];
    const float* W_fuse = (const float*)d_in[13];
    const float* b_fuse = (const float*)d_in[14];
    const float* W_p1   = (const float*)d_in[15];
    const float* b_p1   = (const float*)d_in[16];
    const float* W_p2   = (const float*)d_in[17];
    const float* b_p2   = (const float*)d_in[18];
    const float* W_p3   = (const float*)d_in[19];
    const float* b_p3   = (const float*)d_in[20];
    const float* W_d1   = (const float*)d_in[21];
    const float* b_d1   = (const float*)d_in[22];
    const float* W_d2   = (const float*)d_in[23];
    const float* b_d2   = (const float*)d_in[24];
    const float* W_d3   = (const float*)d_in[25];
    const float* b_d3   = (const float*)d_in[26];

    pack_kernel<<<128, 256>>>((const float4*)W_in, (const float4*)gat_W,
                              (const float4*)W_fuse, (const float4*)W_p1,
                              (const float4*)W_d1, (const float4*)W_p2,
                              (const float4*)W_d2);
    net_kernel<<<64, 512>>>(x, cidx, b_in, gat_b, emb, b_fuse,
                            b_p1, b_d1, b_p2, b_d2,
                            W_p3, b_p3, W_d3, b_d3, (float*)d_out);
}

// round 10
// speedup vs baseline: 1.5751x; 1.1468x over previous
#include <cuda_runtime.h>

// ---------------------------------------------------------------------------
// GAT collapses (uniform per-item node features; per-dst softmax weights sum
// to 1 via self-loops) => whole model = 7-layer MLP on 64 batch rows.
// 32 clusters x 4 CTAs x 512 thr (128 CTAs = full chip). Cluster owns 2 rows;
// each CTA computes 64/256 outputs per layer (360 KB weights/SM), results
// broadcast to 3 peers via st.shared::cluster + barrier.cluster per layer.
// Weight LDGs explicitly batched into register arrays (latency overlap).
// Weights k4-interleaved (packed) -> coalesced LDG.128.
// ---------------------------------------------------------------------------

typedef unsigned long long ULL;
typedef unsigned int U32;

__device__ __forceinline__ void ffma2(ULL& d, ULL a, ULL b) {
    asm("fma.rn.f32x2 %0, %1, %2, %0;" : "+l"(d) : "l"(a), "l"(b));
}
__device__ __forceinline__ void fadd2(ULL& d, ULL a) {
    asm("add.rn.f32x2 %0, %1, %0;" : "+l"(d) : "l"(a));
}
__device__ __forceinline__ float2 unpack2f(ULL v) {
    float2 f; asm("mov.b64 {%0, %1}, %2;" : "=f"(f.x), "=f"(f.y) : "l"(v)); return f;
}
__device__ __forceinline__ U32 smem_u32(const void* p) {
    return (U32)__cvta_generic_to_shared(p);
}
#define CLUSTER_SYNC() do { \
    asm volatile("barrier.cluster.arrive.aligned;" ::: "memory"); \
    asm volatile("barrier.cluster.wait.aligned;"   ::: "memory"); \
} while (0)

// ---- packed weights: quad idx (in region) = k4*O + o ----------------------
#define Q_IN   0        // W_in   256x64   O=256 Kq=16
#define Q_G0   4096     // gat_W0 256x256  O=256 Kq=64
#define Q_G1   20480
#define Q_G2   36864
#define Q_F    53248    // W_fuse 256x320  O=256 Kq=80
#define Q_S1   73728    // [p1;d1] 256x256 O=256 Kq=64
#define Q_2    90112    // [p2;d2] 128x128 O=128 Kq=32
#define Q_TOTAL 94208

__device__ __align__(16) float4 g_packed[Q_TOTAL];

__global__ void pack_kernel(const float4* __restrict__ W_in,
                            const float4* __restrict__ gat_W,
                            const float4* __restrict__ W_fuse,
                            const float4* __restrict__ W_p1,
                            const float4* __restrict__ W_d1,
                            const float4* __restrict__ W_p2,
                            const float4* __restrict__ W_d2) {
    int e = blockIdx.x * blockDim.x + threadIdx.x;   // 184*512 = 94208 exactly
    if (e >= Q_TOTAL) return;
    const float4* src; int le, Kq, Ocomb, obase, offq;
    if (e < 4096)       { src = W_in;          le = e;         Kq = 16; Ocomb = 256; obase = 0;   offq = Q_IN; }
    else if (e < 20480) { src = gat_W;         le = e - 4096;  Kq = 64; Ocomb = 256; obase = 0;   offq = Q_G0; }
    else if (e < 36864) { src = gat_W + 16384; le = e - 20480; Kq = 64; Ocomb = 256; obase = 0;   offq = Q_G1; }
    else if (e < 53248) { src = gat_W + 32768; le = e - 36864; Kq = 64; Ocomb = 256; obase = 0;   offq = Q_G2; }
    else if (e < 73728) { src = W_fuse;        le = e - 53248; Kq = 80; Ocomb = 256; obase = 0;   offq = Q_F;  }
    else if (e < 81920) { src = W_p1;          le = e - 73728; Kq = 64; Ocomb = 256; obase = 0;   offq = Q_S1; }
    else if (e < 90112) { src = W_d1;          le = e - 81920; Kq = 64; Ocomb = 256; obase = 128; offq = Q_S1; }
    else if (e < 92160) { src = W_p2;          le = e - 90112; Kq = 32; Ocomb = 128; obase = 0;   offq = Q_2;  }
    else                { src = W_d2;          le = e - 92160; Kq = 32; Ocomb = 128; obase = 64;  offq = Q_2;  }
    int o  = le / Kq;
    int k4 = le - o * Kq;
    g_packed[offq + k4 * Ocomb + obase + o] = src[o * Kq + k4];
}

__global__ __launch_bounds__(512, 1) __cluster_dims__(4, 1, 1)
void net_kernel(
    const float* __restrict__ x, const int* __restrict__ cidx,
    const float* __restrict__ b_in, const float* __restrict__ gat_b,
    const float* __restrict__ emb, const float* __restrict__ b_fuse,
    const float* __restrict__ b_p1, const float* __restrict__ b_d1,
    const float* __restrict__ b_p2, const float* __restrict__ b_d2,
    const float* __restrict__ W_p3, const float* __restrict__ b_p3,
    const float* __restrict__ W_d3, const float* __restrict__ b_d3,
    float* __restrict__ out) {

    __shared__ __align__(16) float  X[2][64];
    __shared__ __align__(16) float  A[2][336];
    __shared__ __align__(16) float  B[2][336];
    __shared__ __align__(16) float2 P[8][64];
    __shared__ __align__(16) float  C[128];

    const int t  = threadIdx.x;
    const int o  = t & 63;      // output within CTA's 64-slice
    const int kq = t >> 6;      // K eighth 0..7
    U32 rank; asm("mov.u32 %0, %%cluster_ctarank;" : "=r"(rank));
    const int row0 = (blockIdx.x >> 2) * 2;      // cluster's first global row

    // ---- stage inputs locally: x rows -> X; emb[cidx] -> B[r][256..319] ----
    if (t < 32) {
        int r = t >> 4, q = t & 15;
        ((float4*)X[r])[q] = ((const float4*)x)[(row0 + r) * 16 + q];
    } else if (t < 64) {
        int i = t - 32, r = i >> 4, q = i & 15;
        int ci = cidx[row0 + r];
        ((float4*)(B[r] + 256))[q] = ((const float4*)emb)[ci * 16 + q];
    }
    __syncthreads();

    // One layer: CTA computes outputs [rank*64, rank*64+64), K = KQ4*32.
    // Phase 1: batched weight LDG into regs, FFMA2; Phase 2: 8-way smem
    // combine, local + 3 remote stores, cluster sync.
    #define LAYER(QBASE, KQ4, IN, OUT, BIASEXPR)                              \
    {                                                                         \
        const longlong2* Wp = (const longlong2*)g_packed + (QBASE) +          \
            (size_t)(kq * (KQ4)) * 256 + rank * 64 + o;                       \
        const longlong2* a0 = (const longlong2*)IN[0] + kq * (KQ4);           \
        const longlong2* a1 = (const longlong2*)IN[1] + kq * (KQ4);           \
        longlong2 wr[KQ4];                                                    \
        _Pragma("unroll")                                                     \
        for (int i = 0; i < (KQ4); i++) wr[i] = Wp[(size_t)i * 256];          \
        ULL p0 = 0ull, q0 = 0ull, p1 = 0ull, q1 = 0ull;                       \
        _Pragma("unroll")                                                     \
        for (int i = 0; i < (KQ4); i++) {                                     \
            longlong2 x0 = a0[i], x1 = a1[i];                                 \
            ffma2(p0, (ULL)wr[i].x, (ULL)x0.x);                               \
            ffma2(q0, (ULL)wr[i].y, (ULL)x0.y);                               \
            ffma2(p1, (ULL)wr[i].x, (ULL)x1.x);                               \
            ffma2(q1, (ULL)wr[i].y, (ULL)x1.y);                               \
        }                                                                     \
        fadd2(p0, q0); fadd2(p1, q1);                                         \
        float2 f0 = unpack2f(p0), f1 = unpack2f(p1);                          \
        P[kq][o] = make_float2(f0.x + f0.y, f1.x + f1.y);                     \
        __syncthreads();                                                      \
        if (t < 128) {                                                        \
            int rr = t >> 6, oc = t & 63;                                     \
            int ro2 = (int)rank * 64 + oc;                                    \
            float v = 0.f;                                                    \
            _Pragma("unroll")                                                 \
            for (int j = 0; j < 8; j++) {                                     \
                float2 pv = P[j][oc];                                         \
                v += rr ? pv.y : pv.x;                                        \
            }                                                                 \
            float bb = (BIASEXPR);                                            \
            v = fmaxf(v + bb, 0.f);                                           \
            OUT[rr][ro2] = v;                                                 \
            U32 la = smem_u32(&OUT[rr][ro2]);                                 \
            _Pragma("unroll")                                                 \
            for (int p = 0; p < 4; p++) if (p != (int)rank) {                 \
                U32 pa;                                                       \
                asm("mapa.shared::cluster.u32 %0, %1, %2;"                    \
                    : "=r"(pa) : "r"(la), "r"(p));                            \
                asm volatile("st.shared::cluster.f32 [%0], %1;"               \
                             :: "r"(pa), "f"(v) : "memory");                  \
            }                                                                 \
        }                                                                     \
        CLUSTER_SYNC();                                                       \
    }

    // L0: [256x64]  X -> A
    LAYER(Q_IN, 2,  X, A, b_in[ro2]);
    // L1..L3: collapsed GAT [256x256]
    LAYER(Q_G0, 8,  A, B, gat_b[ro2]);
    LAYER(Q_G1, 8,  B, A, gat_b[256 + ro2]);
    LAYER(Q_G2, 8,  A, B, gat_b[512 + ro2]);
    // L4: fuse [256x320] over [g3 ; emb] (emb pre-staged in B[r][256..319])
    LAYER(Q_F,  10, B, A, b_fuse[ro2]);
    // L5: heads stage1 [p1 ; d1] = [256x256]
    LAYER(Q_S1, 8,  A, B, (ro2 < 128) ? b_p1[ro2] : b_d1[ro2 - 128]);
    #undef LAYER

    // ---- Tail (CTA-local): ranks 0,1 own rows row0+rank; acts replicated. --
    if ((int)rank < 2) {
        const float* Brow = B[rank];
        float* Ps = (float*)P;                       // scratch [4][128]
        const int kq2 = t >> 7;                      // K quarter 0..3
        const int o2  = t & 127;                     // 0..63 p2, 64..127 d2
        // L6: [p2;d2] 128 outs, K=128
        {
            const longlong2* Wp = (const longlong2*)g_packed + Q_2 +
                (size_t)(kq2 * 8) * 128 + o2;
            const longlong2* Aq = (const longlong2*)Brow +
                ((o2 >= 64) ? 32 : 0) + kq2 * 8;
            longlong2 wr[8];
            #pragma unroll
            for (int i = 0; i < 8; i++) wr[i] = Wp[(size_t)i * 128];
            ULL p0 = 0ull, q0 = 0ull;
            #pragma unroll
            for (int i = 0; i < 8; i++) {
                longlong2 x0 = Aq[i];
                ffma2(p0, (ULL)wr[i].x, (ULL)x0.x);
                ffma2(q0, (ULL)wr[i].y, (ULL)x0.y);
            }
            fadd2(p0, q0);
            float2 f0 = unpack2f(p0);
            Ps[kq2 * 128 + o2] = f0.x + f0.y;
        }
        __syncthreads();
        if (t < 128) {
            float b2 = (t < 64) ? b_p2[t] : b_d2[t - 64];
            C[t] = fmaxf(Ps[t] + Ps[128 + t] + Ps[256 + t] + Ps[384 + t] + b2, 0.f);
        }
        __syncthreads();
        // L7: price (warp 0) / direction (warp 1)
        const int w = t >> 5, lane = t & 31;
        if (w < 2) {
            const float* W3 = w ? W_d3 : W_p3;
            const float* Cv = C + w * 64;
            float v = W3[lane] * Cv[lane] + W3[lane + 32] * Cv[lane + 32];
            #pragma unroll
            for (int m = 16; m; m >>= 1)
                v += __shfl_xor_sync(0xffffffffu, v, m);
            if (lane == 0) {
                int rg = row0 + (int)rank;
                if (!w) out[rg] = v + b_p3[0];
                else    out[64 + rg] = 1.f / (1.f + __expf(-(v + b_d3[0])));
            }
        }
    }
}

extern "C" void kernel_launch(void* const* d_in, const int* in_sizes, int n_in,
                              void* d_out, int out_size) {
    const float* x      = (const float*)d_in[0];
    const int*   cidx   = (const int*)  d_in[1];
    // d_in[2] edge_index, d_in[3] edge_attr: unused (softmax collapse)
    const float* W_in   = (const float*)d_in[4];
    const float* b_in   = (const float*)d_in[5];
    const float* gat_W  = (const float*)d_in[6];
    // d_in[7..10]: attention params — unused (collapse)
    const float* gat_b  = (const float*)d_in[11];
    const float* emb    = (const float*)d_in[12];
    const float* W_fuse = (const float*)d_in[13];
    const float* b_fuse = (const float*)d_in[14];
    const float* W_p1   = (const float*)d_in[15];
    const float* b_p1   = (const float*)d_in[16];
    const float* W_p2   = (const float*)d_in[17];
    const float* b_p2   = (const float*)d_in[18];
    const float* W_p3   = (const float*)d_in[19];
    const float* b_p3   = (const float*)d_in[20];
    const float* W_d1   = (const float*)d_in[21];
    const float* b_d1   = (const float*)d_in[22];
    const float* W_d2   = (const float*)d_in[23];
    const float* b_d2   = (const float*)d_in[24];
    const float* W_d3   = (const float*)d_in[25];
    const float* b_d3   = (const float*)d_in[26];

    pack_kernel<<<184, 512>>>((const float4*)W_in, (const float4*)gat_W,
                              (const float4*)W_fuse, (const float4*)W_p1,
                              (const float4*)W_d1, (const float4*)W_p2,
                              (const float4*)W_d2);
    net_kernel<<<128, 512>>>(x, cidx, b_in, gat_b, emb, b_fuse,
                             b_p1, b_d1, b_p2, b_d2,
                             W_p3, b_p3, W_d3, b_d3, (float*)d_out);
}

// round 11
// speedup vs baseline: 1.7015x; 1.0802x over previous
#include <cuda_runtime.h>

// ---------------------------------------------------------------------------
// GAT collapses (uniform per-item node features; per-dst softmax weights sum
// to 1 via self-loops) => whole model = 7-layer MLP on 64 batch rows.
// 32 clusters x 4 CTAs x 512 thr (128 CTAs = full chip). Cluster owns 2 rows;
// each CTA computes 64/256 outputs per layer; results broadcast to 3 peers
// via st.shared::cluster + barrier.cluster per layer.
// NEW: next layer's weight LDGs are issued between cluster arrive and wait,
// hiding L2 latency under the barrier (weight addresses are static).
// Weights k4-interleaved (packed) -> coalesced LDG.128.
// ---------------------------------------------------------------------------

typedef unsigned long long ULL;
typedef unsigned int U32;

__device__ __forceinline__ void ffma2(ULL& d, ULL a, ULL b) {
    asm("fma.rn.f32x2 %0, %1, %2, %0;" : "+l"(d) : "l"(a), "l"(b));
}
__device__ __forceinline__ void fadd2(ULL& d, ULL a) {
    asm("add.rn.f32x2 %0, %1, %0;" : "+l"(d) : "l"(a));
}
__device__ __forceinline__ float2 unpack2f(ULL v) {
    float2 f; asm("mov.b64 {%0, %1}, %2;" : "=f"(f.x), "=f"(f.y) : "l"(v)); return f;
}
__device__ __forceinline__ U32 smem_u32(const void* p) {
    return (U32)__cvta_generic_to_shared(p);
}
#define CLUSTER_ARRIVE() asm volatile("barrier.cluster.arrive.aligned;" ::: "memory")
#define CLUSTER_WAIT()   asm volatile("barrier.cluster.wait.aligned;"   ::: "memory")

// ---- packed weights: quad idx (in region) = k4*O + o ----------------------
#define Q_IN   0        // W_in   256x64   O=256 Kq=16
#define Q_G0   4096     // gat_W0 256x256  O=256 Kq=64
#define Q_G1   20480
#define Q_G2   36864
#define Q_F    53248    // W_fuse 256x320  O=256 Kq=80
#define Q_S1   73728    // [p1;d1] 256x256 O=256 Kq=64
#define Q_2    90112    // [p2;d2] 128x128 O=128 Kq=32
#define Q_TOTAL 94208

__device__ __align__(16) float4 g_packed[Q_TOTAL];

__global__ void pack_kernel(const float4* __restrict__ W_in,
                            const float4* __restrict__ gat_W,
                            const float4* __restrict__ W_fuse,
                            const float4* __restrict__ W_p1,
                            const float4* __restrict__ W_d1,
                            const float4* __restrict__ W_p2,
                            const float4* __restrict__ W_d2) {
    int e = blockIdx.x * blockDim.x + threadIdx.x;   // 184*512 = 94208 exactly
    if (e >= Q_TOTAL) return;
    const float4* src; int le, Kq, Ocomb, obase, offq;
    if (e < 4096)       { src = W_in;          le = e;         Kq = 16; Ocomb = 256; obase = 0;   offq = Q_IN; }
    else if (e < 20480) { src = gat_W;         le = e - 4096;  Kq = 64; Ocomb = 256; obase = 0;   offq = Q_G0; }
    else if (e < 36864) { src = gat_W + 16384; le = e - 20480; Kq = 64; Ocomb = 256; obase = 0;   offq = Q_G1; }
    else if (e < 53248) { src = gat_W + 32768; le = e - 36864; Kq = 64; Ocomb = 256; obase = 0;   offq = Q_G2; }
    else if (e < 73728) { src = W_fuse;        le = e - 53248; Kq = 80; Ocomb = 256; obase = 0;   offq = Q_F;  }
    else if (e < 81920) { src = W_p1;          le = e - 73728; Kq = 64; Ocomb = 256; obase = 0;   offq = Q_S1; }
    else if (e < 90112) { src = W_d1;          le = e - 81920; Kq = 64; Ocomb = 256; obase = 128; offq = Q_S1; }
    else if (e < 92160) { src = W_p2;          le = e - 90112; Kq = 32; Ocomb = 128; obase = 0;   offq = Q_2;  }
    else                { src = W_d2;          le = e - 92160; Kq = 32; Ocomb = 128; obase = 64;  offq = Q_2;  }
    int o  = le / Kq;
    int k4 = le - o * Kq;
    g_packed[offq + k4 * Ocomb + obase + o] = src[o * Kq + k4];
}

template<int N, int STRIDE>
__device__ __forceinline__ void loadw(longlong2* wr, const longlong2* Wp) {
    #pragma unroll
    for (int i = 0; i < N; i++) wr[i] = Wp[(size_t)i * STRIDE];
}

__global__ __launch_bounds__(512, 1) __cluster_dims__(4, 1, 1)
void net_kernel(
    const float* __restrict__ x, const int* __restrict__ cidx,
    const float* __restrict__ b_in, const float* __restrict__ gat_b,
    const float* __restrict__ emb, const float* __restrict__ b_fuse,
    const float* __restrict__ b_p1, const float* __restrict__ b_d1,
    const float* __restrict__ b_p2, const float* __restrict__ b_d2,
    const float* __restrict__ W_p3, const float* __restrict__ b_p3,
    const float* __restrict__ W_d3, const float* __restrict__ b_d3,
    float* __restrict__ out) {

    __shared__ __align__(16) float  X[2][64];
    __shared__ __align__(16) float  A[2][336];
    __shared__ __align__(16) float  B[2][336];
    __shared__ __align__(16) float2 P[8][64];
    __shared__ __align__(16) float  C[128];

    const int t  = threadIdx.x;
    const int o  = t & 63;      // output within CTA's 64-slice
    const int kq = t >> 6;      // K eighth 0..7
    U32 rank; asm("mov.u32 %0, %%cluster_ctarank;" : "=r"(rank));
    const int row0 = (blockIdx.x >> 2) * 2;      // cluster's first global row
    const int kq2 = t >> 7;                      // tail: K quarter 0..3
    const int o2  = t & 127;                     // tail: 0..63 p2, 64..127 d2

    const longlong2* GP = (const longlong2*)g_packed;
    longlong2 wr[10];

    // Prefetch L0 weights immediately.
    loadw<2, 256>(wr, GP + Q_IN + (size_t)(kq * 2) * 256 + rank * 64 + o);

    // ---- stage inputs locally: x rows -> X; emb[cidx] -> B[r][256..319] ----
    if (t < 32) {
        int r = t >> 4, q = t & 15;
        ((float4*)X[r])[q] = ((const float4*)x)[(row0 + r) * 16 + q];
    } else if (t < 64) {
        int i = t - 32, r = i >> 4, q = i & 15;
        int ci = cidx[row0 + r];
        ((float4*)(B[r] + 256))[q] = ((const float4*)emb)[ci * 16 + q];
    }
    __syncthreads();

    // FFMA phase over this thread's K-slice; partials into P.
    #define COMPUTE(KQ4, IN)                                                  \
    {                                                                         \
        const longlong2* a0 = (const longlong2*)IN[0] + kq * (KQ4);           \
        const longlong2* a1 = (const longlong2*)IN[1] + kq * (KQ4);           \
        ULL p0 = 0ull, q0 = 0ull, p1 = 0ull, q1 = 0ull;                       \
        _Pragma("unroll")                                                     \
        for (int i = 0; i < (KQ4); i++) {                                     \
            longlong2 x0 = a0[i], x1 = a1[i];                                 \
            ffma2(p0, (ULL)wr[i].x, (ULL)x0.x);                               \
            ffma2(q0, (ULL)wr[i].y, (ULL)x0.y);                               \
            ffma2(p1, (ULL)wr[i].x, (ULL)x1.x);                               \
            ffma2(q1, (ULL)wr[i].y, (ULL)x1.y);                               \
        }                                                                     \
        fadd2(p0, q0); fadd2(p1, q1);                                         \
        float2 f0 = unpack2f(p0), f1 = unpack2f(p1);                          \
        P[kq][o] = make_float2(f0.x + f0.y, f1.x + f1.y);                     \
    }

    // Combine + broadcast + barrier; PREFETCH (statement) between arrive/wait.
    #define EXCHANGE(OUT, BIASEXPR, PREFETCH)                                 \
    {                                                                         \
        __syncthreads();                                                      \
        if (t < 128) {                                                        \
            int rr = t >> 6, oc = t & 63;                                     \
            int ro2 = (int)rank * 64 + oc;                                    \
            float v = 0.f;                                                    \
            _Pragma("unroll")                                                 \
            for (int j = 0; j < 8; j++) {                                     \
                float2 pv = P[j][oc];                                         \
                v += rr ? pv.y : pv.x;                                        \
            }                                                                 \
            float bb = (BIASEXPR);                                            \
            v = fmaxf(v + bb, 0.f);                                           \
            OUT[rr][ro2] = v;                                                 \
            U32 la = smem_u32(&OUT[rr][ro2]);                                 \
            _Pragma("unroll")                                                 \
            for (int p = 0; p < 4; p++) if (p != (int)rank) {                 \
                U32 pa;                                                       \
                asm("mapa.shared::cluster.u32 %0, %1, %2;"                    \
                    : "=r"(pa) : "r"(la), "r"(p));                            \
                asm volatile("st.shared::cluster.f32 [%0], %1;"               \
                             :: "r"(pa), "f"(v) : "memory");                  \
            }                                                                 \
        }                                                                     \
        CLUSTER_ARRIVE();                                                     \
        PREFETCH();                                                           \
        CLUSTER_WAIT();                                                       \
    }

    auto pf_g0 = [&] { loadw<8, 256>(wr, GP + Q_G0 + (size_t)(kq * 8) * 256 + rank * 64 + o); };
    auto pf_g1 = [&] { loadw<8, 256>(wr, GP + Q_G1 + (size_t)(kq * 8) * 256 + rank * 64 + o); };
    auto pf_g2 = [&] { loadw<8, 256>(wr, GP + Q_G2 + (size_t)(kq * 8) * 256 + rank * 64 + o); };
    auto pf_f  = [&] { loadw<10, 256>(wr, GP + Q_F + (size_t)(kq * 10) * 256 + rank * 64 + o); };
    auto pf_s1 = [&] { loadw<8, 256>(wr, GP + Q_S1 + (size_t)(kq * 8) * 256 + rank * 64 + o); };
    auto pf_t  = [&] { loadw<8, 128>(wr, GP + Q_2 + (size_t)(kq2 * 8) * 128 + o2); };

    // L0: [256x64]  X -> A
    COMPUTE(2, X);
    EXCHANGE(A, b_in[ro2], pf_g0);
    // L1..L3: collapsed GAT [256x256]
    COMPUTE(8, A);
    EXCHANGE(B, gat_b[ro2], pf_g1);
    COMPUTE(8, B);
    EXCHANGE(A, gat_b[256 + ro2], pf_g2);
    COMPUTE(8, A);
    EXCHANGE(B, gat_b[512 + ro2], pf_f);
    // L4: fuse [256x320] over [g3 ; emb] (emb pre-staged in B[r][256..319])
    COMPUTE(10, B);
    EXCHANGE(A, b_fuse[ro2], pf_s1);
    // L5: heads stage1 [p1 ; d1] = [256x256]
    COMPUTE(8, A);
    EXCHANGE(B, (ro2 < 128) ? b_p1[ro2] : b_d1[ro2 - 128], pf_t);
    #undef COMPUTE
    #undef EXCHANGE

    // ---- Tail (CTA-local): ranks 0,1 own rows row0+rank; acts replicated. --
    if ((int)rank < 2) {
        const float* Brow = B[rank];
        float* Ps = (float*)P;                       // scratch [4][128]
        // L6: [p2;d2] 128 outs, K=128 (weights already prefetched in wr)
        {
            const longlong2* Aq = (const longlong2*)Brow +
                ((o2 >= 64) ? 32 : 0) + kq2 * 8;
            ULL p0 = 0ull, q0 = 0ull;
            #pragma unroll
            for (int i = 0; i < 8; i++) {
                longlong2 x0 = Aq[i];
                ffma2(p0, (ULL)wr[i].x, (ULL)x0.x);
                ffma2(q0, (ULL)wr[i].y, (ULL)x0.y);
            }
            fadd2(p0, q0);
            float2 f0 = unpack2f(p0);
            Ps[kq2 * 128 + o2] = f0.x + f0.y;
        }
        __syncthreads();
        if (t < 128) {
            float b2 = (t < 64) ? b_p2[t] : b_d2[t - 64];
            C[t] = fmaxf(Ps[t] + Ps[128 + t] + Ps[256 + t] + Ps[384 + t] + b2, 0.f);
        }
        __syncthreads();
        // L7: price (warp 0) / direction (warp 1)
        const int w = t >> 5, lane = t & 31;
        if (w < 2) {
            const float* W3 = w ? W_d3 : W_p3;
            const float* Cv = C + w * 64;
            float v = W3[lane] * Cv[lane] + W3[lane + 32] * Cv[lane + 32];
            #pragma unroll
            for (int m = 16; m; m >>= 1)
                v += __shfl_xor_sync(0xffffffffu, v, m);
            if (lane == 0) {
                int rg = row0 + (int)rank;
                if (!w) out[rg] = v + b_p3[0];
                else    out[64 + rg] = 1.f / (1.f + __expf(-(v + b_d3[0])));
            }
        }
    }
}

extern "C" void kernel_launch(void* const* d_in, const int* in_sizes, int n_in,
                              void* d_out, int out_size) {
    const float* x      = (const float*)d_in[0];
    const int*   cidx   = (const int*)  d_in[1];
    // d_in[2] edge_index, d_in[3] edge_attr: unused (softmax collapse)
    const float* W_in   = (const float*)d_in[4];
    const float* b_in   = (const float*)d_in[5];
    const float* gat_W  = (const float*)d_in[6];
    // d_in[7..10]: attention params — unused (collapse)
    const float* gat_b  = (const float*)d_in[11];
    const float* emb    = (const float*)d_in[12];
    const float* W_fuse = (const float*)d_in[13];
    const float* b_fuse = (const float*)d_in[14];
    const float* W_p1   = (const float*)d_in[15];
    const float* b_p1   = (const float*)d_in[16];
    const float* W_p2   = (const float*)d_in[17];
    const float* b_p2   = (const float*)d_in[18];
    const float* W_p3   = (const float*)d_in[19];
    const float* b_p3   = (const float*)d_in[20];
    const float* W_d1   = (const float*)d_in[21];
    const float* b_d1   = (const float*)d_in[22];
    const float* W_d2   = (const float*)d_in[23];
    const float* b_d2   = (const float*)d_in[24];
    const float* W_d3   = (const float*)d_in[25];
    const float* b_d3   = (const float*)d_in[26];

    pack_kernel<<<184, 512>>>((const float4*)W_in, (const float4*)gat_W,
                              (const float4*)W_fuse, (const float4*)W_p1,
                              (const float4*)W_d1, (const float4*)W_p2,
                              (const float4*)W_d2);
    net_kernel<<<128, 512>>>(x, cidx, b_in, gat_b, emb, b_fuse,
                             b_p1, b_d1, b_p2, b_d2,
                             W_p3, b_p3, W_d3, b_d3, (float*)d_out);
}

// round 12
// speedup vs baseline: 1.7047x; 1.0019x over previous
#include <cuda_runtime.h>

// ---------------------------------------------------------------------------
// GAT collapses (uniform per-item node features; per-dst softmax weights sum
// to 1 via self-loops) => whole model = 7-layer MLP on 64 batch rows.
// 32 clusters x 4 CTAs x 512 thr (128 CTAs = full chip). Cluster owns 2 rows;
// each CTA computes 64/256 outputs per big layer; results broadcast to peers
// via st.shared::cluster + barrier.cluster. Next layer's weight LDGs issue
// between cluster arrive and wait (latency hidden under barrier).
// NEW: PDL overlaps net_kernel's input staging with pack_kernel;
//      L0 computed CTA-locally (no exchange/barrier);
//      last exchange stores only to the tail-owner peers.
// ---------------------------------------------------------------------------

typedef unsigned long long ULL;
typedef unsigned int U32;

__device__ __forceinline__ void ffma2(ULL& d, ULL a, ULL b) {
    asm("fma.rn.f32x2 %0, %1, %2, %0;" : "+l"(d) : "l"(a), "l"(b));
}
__device__ __forceinline__ void fadd2(ULL& d, ULL a) {
    asm("add.rn.f32x2 %0, %1, %0;" : "+l"(d) : "l"(a));
}
__device__ __forceinline__ float2 unpack2f(ULL v) {
    float2 f; asm("mov.b64 {%0, %1}, %2;" : "=f"(f.x), "=f"(f.y) : "l"(v)); return f;
}
__device__ __forceinline__ U32 smem_u32(const void* p) {
    return (U32)__cvta_generic_to_shared(p);
}
#define CLUSTER_ARRIVE() asm volatile("barrier.cluster.arrive.aligned;" ::: "memory")
#define CLUSTER_WAIT()   asm volatile("barrier.cluster.wait.aligned;"   ::: "memory")

// ---- packed weights: quad idx (in region) = k4*O + o ----------------------
#define Q_IN   0        // W_in   256x64   O=256 Kq=16
#define Q_G0   4096     // gat_W0 256x256  O=256 Kq=64
#define Q_G1   20480
#define Q_G2   36864
#define Q_F    53248    // W_fuse 256x320  O=256 Kq=80
#define Q_S1   73728    // [p1;d1] 256x256 O=256 Kq=64
#define Q_2    90112    // [p2;d2] 128x128 O=128 Kq=32
#define Q_TOTAL 94208

__device__ __align__(16) float4 g_packed[Q_TOTAL];

__global__ void pack_kernel(const float4* __restrict__ W_in,
                            const float4* __restrict__ gat_W,
                            const float4* __restrict__ W_fuse,
                            const float4* __restrict__ W_p1,
                            const float4* __restrict__ W_d1,
                            const float4* __restrict__ W_p2,
                            const float4* __restrict__ W_d2) {
    int e = blockIdx.x * blockDim.x + threadIdx.x;   // 184*512 = 94208 exactly
    if (e < Q_TOTAL) {
        const float4* src; int le, Kq, Ocomb, obase, offq;
        if (e < 4096)       { src = W_in;          le = e;         Kq = 16; Ocomb = 256; obase = 0;   offq = Q_IN; }
        else if (e < 20480) { src = gat_W;         le = e - 4096;  Kq = 64; Ocomb = 256; obase = 0;   offq = Q_G0; }
        else if (e < 36864) { src = gat_W + 16384; le = e - 20480; Kq = 64; Ocomb = 256; obase = 0;   offq = Q_G1; }
        else if (e < 53248) { src = gat_W + 32768; le = e - 36864; Kq = 64; Ocomb = 256; obase = 0;   offq = Q_G2; }
        else if (e < 73728) { src = W_fuse;        le = e - 53248; Kq = 80; Ocomb = 256; obase = 0;   offq = Q_F;  }
        else if (e < 81920) { src = W_p1;          le = e - 73728; Kq = 64; Ocomb = 256; obase = 0;   offq = Q_S1; }
        else if (e < 90112) { src = W_d1;          le = e - 81920; Kq = 64; Ocomb = 256; obase = 128; offq = Q_S1; }
        else if (e < 92160) { src = W_p2;          le = e - 90112; Kq = 32; Ocomb = 128; obase = 0;   offq = Q_2;  }
        else                { src = W_d2;          le = e - 92160; Kq = 32; Ocomb = 128; obase = 64;  offq = Q_2;  }
        int o  = le / Kq;
        int k4 = le - o * Kq;
        g_packed[offq + k4 * Ocomb + obase + o] = src[le];   // coalesced read
    }
    // Signal programmatic dependents (net_kernel) once all CTAs reach here.
    asm volatile("griddepcontrol.launch_dependents;" ::: "memory");
}

template<int N, int STRIDE>
__device__ __forceinline__ void loadw(longlong2* wr, const longlong2* Wp) {
    #pragma unroll
    for (int i = 0; i < N; i++) wr[i] = Wp[(size_t)i * STRIDE];
}

__global__ __launch_bounds__(512, 1) __cluster_dims__(4, 1, 1)
void net_kernel(
    const float* __restrict__ x, const int* __restrict__ cidx,
    const float* __restrict__ b_in, const float* __restrict__ gat_b,
    const float* __restrict__ emb, const float* __restrict__ b_fuse,
    const float* __restrict__ b_p1, const float* __restrict__ b_d1,
    const float* __restrict__ b_p2, const float* __restrict__ b_d2,
    const float* __restrict__ W_p3, const float* __restrict__ b_p3,
    const float* __restrict__ W_d3, const float* __restrict__ b_d3,
    float* __restrict__ out) {

    __shared__ __align__(16) float  X[2][64];
    __shared__ __align__(16) float  A[2][336];
    __shared__ __align__(16) float  B[2][336];
    __shared__ __align__(16) float2 P[8][64];
    __shared__ __align__(16) float  C[128];

    const int t  = threadIdx.x;
    const int o  = t & 63;      // output within CTA's 64-slice (big layers)
    const int kq = t >> 6;      // K eighth 0..7
    U32 rank; asm("mov.u32 %0, %%cluster_ctarank;" : "=r"(rank));
    const int row0 = (blockIdx.x >> 2) * 2;      // cluster's first global row
    const int kq2 = t >> 7;                      // tail: K quarter 0..3
    const int o2  = t & 127;                     // tail: 0..63 p2, 64..127 d2
    const int oc0 = t & 255, kh0 = t >> 8;       // L0-local mapping

    const longlong2* GP = (const longlong2*)g_packed;
    longlong2 wr[10];

    // ---- stage inputs (independent of pack output) ----
    if (t < 32) {
        int r = t >> 4, q = t & 15;
        ((float4*)X[r])[q] = ((const float4*)x)[(row0 + r) * 16 + q];
    } else if (t < 64) {
        int i = t - 32, r = i >> 4, q = i & 15;
        int ci = cidx[row0 + r];
        ((float4*)(B[r] + 256))[q] = ((const float4*)emb)[ci * 16 + q];
    }

    // ---- wait for pack_kernel's writes to be visible (PDL) ----
    asm volatile("griddepcontrol.wait;" ::: "memory");
    __syncthreads();

    // ===== L0 (CTA-local, all 256 outputs, K=64): X -> A =====
    {
        float2 (*P2)[256] = (float2 (*)[256])&P[0][0];
        loadw<8, 256>(wr, GP + Q_IN + (size_t)(kh0 * 8) * 256 + oc0);
        const longlong2* a0 = (const longlong2*)X[0] + kh0 * 8;
        const longlong2* a1 = (const longlong2*)X[1] + kh0 * 8;
        ULL p0 = 0ull, q0 = 0ull, p1 = 0ull, q1 = 0ull;
        #pragma unroll
        for (int i = 0; i < 8; i++) {
            longlong2 x0 = a0[i], x1 = a1[i];
            ffma2(p0, (ULL)wr[i].x, (ULL)x0.x);
            ffma2(q0, (ULL)wr[i].y, (ULL)x0.y);
            ffma2(p1, (ULL)wr[i].x, (ULL)x1.x);
            ffma2(q1, (ULL)wr[i].y, (ULL)x1.y);
        }
        fadd2(p0, q0); fadd2(p1, q1);
        float2 f0 = unpack2f(p0), f1 = unpack2f(p1);
        P2[kh0][oc0] = make_float2(f0.x + f0.y, f1.x + f1.y);
        // Prefetch L1 weights while partials settle.
        loadw<8, 256>(wr, GP + Q_G0 + (size_t)(kq * 8) * 256 + rank * 64 + o);
        __syncthreads();
        {
            int rr = t >> 8, oc = t & 255;
            float v = rr ? (P2[0][oc].y + P2[1][oc].y)
                         : (P2[0][oc].x + P2[1][oc].x);
            A[rr][oc] = fmaxf(v + b_in[oc], 0.f);
        }
        __syncthreads();
    }

    // FFMA phase over this thread's K-slice; partials into P.
    #define COMPUTE(KQ4, IN)                                                  \
    {                                                                         \
        const longlong2* a0 = (const longlong2*)IN[0] + kq * (KQ4);           \
        const longlong2* a1 = (const longlong2*)IN[1] + kq * (KQ4);           \
        ULL p0 = 0ull, q0 = 0ull, p1 = 0ull, q1 = 0ull;                       \
        _Pragma("unroll")                                                     \
        for (int i = 0; i < (KQ4); i++) {                                     \
            longlong2 x0 = a0[i], x1 = a1[i];                                 \
            ffma2(p0, (ULL)wr[i].x, (ULL)x0.x);                               \
            ffma2(q0, (ULL)wr[i].y, (ULL)x0.y);                               \
            ffma2(p1, (ULL)wr[i].x, (ULL)x1.x);                               \
            ffma2(q1, (ULL)wr[i].y, (ULL)x1.y);                               \
        }                                                                     \
        fadd2(p0, q0); fadd2(p1, q1);                                         \
        float2 f0 = unpack2f(p0), f1 = unpack2f(p1);                          \
        P[kq][o] = make_float2(f0.x + f0.y, f1.x + f1.y);                     \
    }

    // Combine + broadcast to NPEER peers + barrier; PREFETCH between
    // arrive/wait. NPEER=3: all peers; NPEER=1: only tail owners (ranks 0,1).
    #define EXCHANGE(OUT, BIASEXPR, PREFETCH, ALLPEERS)                       \
    {                                                                         \
        __syncthreads();                                                      \
        if (t < 128) {                                                        \
            int rr = t >> 6, oc = t & 63;                                     \
            int ro2 = (int)rank * 64 + oc;                                    \
            float v = 0.f;                                                    \
            _Pragma("unroll")                                                 \
            for (int j = 0; j < 8; j++) {                                     \
                float2 pv = P[j][oc];                                         \
                v += rr ? pv.y : pv.x;                                        \
            }                                                                 \
            float bb = (BIASEXPR);                                            \
            v = fmaxf(v + bb, 0.f);                                           \
            OUT[rr][ro2] = v;                                                 \
            U32 la = smem_u32(&OUT[rr][ro2]);                                 \
            if (ALLPEERS) {                                                   \
                _Pragma("unroll")                                             \
                for (int p = 0; p < 4; p++) if (p != (int)rank) {             \
                    U32 pa;                                                   \
                    asm("mapa.shared::cluster.u32 %0, %1, %2;"                \
                        : "=r"(pa) : "r"(la), "r"(p));                        \
                    asm volatile("st.shared::cluster.f32 [%0], %1;"           \
                                 :: "r"(pa), "f"(v) : "memory");              \
                }                                                             \
            } else {                                                          \
                if (rr != (int)rank) {                                        \
                    U32 pa;                                                   \
                    asm("mapa.shared::cluster.u32 %0, %1, %2;"                \
                        : "=r"(pa) : "r"(la), "r"(rr));                       \
                    asm volatile("st.shared::cluster.f32 [%0], %1;"           \
                                 :: "r"(pa), "f"(v) : "memory");              \
                }                                                             \
            }                                                                 \
        }                                                                     \
        CLUSTER_ARRIVE();                                                     \
        PREFETCH();                                                           \
        CLUSTER_WAIT();                                                       \
    }

    auto pf_g1 = [&] { loadw<8, 256>(wr, GP + Q_G1 + (size_t)(kq * 8) * 256 + rank * 64 + o); };
    auto pf_g2 = [&] { loadw<8, 256>(wr, GP + Q_G2 + (size_t)(kq * 8) * 256 + rank * 64 + o); };
    auto pf_f  = [&] { loadw<10, 256>(wr, GP + Q_F + (size_t)(kq * 10) * 256 + rank * 64 + o); };
    auto pf_s1 = [&] { loadw<8, 256>(wr, GP + Q_S1 + (size_t)(kq * 8) * 256 + rank * 64 + o); };
    auto pf_t  = [&] { loadw<8, 128>(wr, GP + Q_2 + (size_t)(kq2 * 8) * 128 + o2); };

    // L1..L3: collapsed GAT [256x256]
    COMPUTE(8, A);
    EXCHANGE(B, gat_b[ro2], pf_g1, 1);
    COMPUTE(8, B);
    EXCHANGE(A, gat_b[256 + ro2], pf_g2, 1);
    COMPUTE(8, A);
    EXCHANGE(B, gat_b[512 + ro2], pf_f, 1);
    // L4: fuse [256x320] over [g3 ; emb] (emb pre-staged in B[r][256..319])
    COMPUTE(10, B);
    EXCHANGE(A, b_fuse[ro2], pf_s1, 1);
    // L5: heads stage1 [p1 ; d1] = [256x256]; only tail owners need results.
    COMPUTE(8, A);
    EXCHANGE(B, (ro2 < 128) ? b_p1[ro2] : b_d1[ro2 - 128], pf_t, 0);
    #undef COMPUTE
    #undef EXCHANGE

    // ---- Tail (CTA-local): ranks 0,1 own rows row0+rank. ----
    if ((int)rank < 2) {
        const float* Brow = B[rank];
        float* Ps = (float*)P;                       // scratch [4][128]
        // L6: [p2;d2] 128 outs, K=128 (weights already prefetched in wr)
        {
            const longlong2* Aq = (const longlong2*)Brow +
                ((o2 >= 64) ? 32 : 0) + kq2 * 8;
            ULL p0 = 0ull, q0 = 0ull;
            #pragma unroll
            for (int i = 0; i < 8; i++) {
                longlong2 x0 = Aq[i];
                ffma2(p0, (ULL)wr[i].x, (ULL)x0.x);
                ffma2(q0, (ULL)wr[i].y, (ULL)x0.y);
            }
            fadd2(p0, q0);
            float2 f0 = unpack2f(p0);
            Ps[kq2 * 128 + o2] = f0.x + f0.y;
        }
        __syncthreads();
        if (t < 128) {
            float b2 = (t < 64) ? b_p2[t] : b_d2[t - 64];
            C[t] = fmaxf(Ps[t] + Ps[128 + t] + Ps[256 + t] + Ps[384 + t] + b2, 0.f);
        }
        __syncthreads();
        // L7: price (warp 0) / direction (warp 1)
        const int w = t >> 5, lane = t & 31;
        if (w < 2) {
            const float* W3 = w ? W_d3 : W_p3;
            const float* Cv = C + w * 64;
            float v = W3[lane] * Cv[lane] + W3[lane + 32] * Cv[lane + 32];
            #pragma unroll
            for (int m = 16; m; m >>= 1)
                v += __shfl_xor_sync(0xffffffffu, v, m);
            if (lane == 0) {
                int rg = row0 + (int)rank;
                if (!w) out[rg] = v + b_p3[0];
                else    out[64 + rg] = 1.f / (1.f + __expf(-(v + b_d3[0])));
            }
        }
    }
}

extern "C" void kernel_launch(void* const* d_in, const int* in_sizes, int n_in,
                              void* d_out, int out_size) {
    const float* x      = (const float*)d_in[0];
    const int*   cidx   = (const int*)  d_in[1];
    // d_in[2] edge_index, d_in[3] edge_attr: unused (softmax collapse)
    const float* W_in   = (const float*)d_in[4];
    const float* b_in   = (const float*)d_in[5];
    const float* gat_W  = (const float*)d_in[6];
    // d_in[7..10]: attention params — unused (collapse)
    const float* gat_b  = (const float*)d_in[11];
    const float* emb    = (const float*)d_in[12];
    const float* W_fuse = (const float*)d_in[13];
    const float* b_fuse = (const float*)d_in[14];
    const float* W_p1   = (const float*)d_in[15];
    const float* b_p1   = (const float*)d_in[16];
    const float* W_p2   = (const float*)d_in[17];
    const float* b_p2   = (const float*)d_in[18];
    const float* W_p3   = (const float*)d_in[19];
    const float* b_p3   = (const float*)d_in[20];
    const float* W_d1   = (const float*)d_in[21];
    const float* b_d1   = (const float*)d_in[22];
    const float* W_d2   = (const float*)d_in[23];
    const float* b_d2   = (const float*)d_in[24];
    const float* W_d3   = (const float*)d_in[25];
    const float* b_d3   = (const float*)d_in[26];

    pack_kernel<<<184, 512>>>((const float4*)W_in, (const float4*)gat_W,
                              (const float4*)W_fuse, (const float4*)W_p1,
                              (const float4*)W_d1, (const float4*)W_p2,
                              (const float4*)W_d2);

    // Launch net_kernel with programmatic dependent launch: it starts while
    // pack_kernel drains, stages inputs, then griddepcontrol.wait's.
    cudaLaunchConfig_t cfg = {};
    cfg.gridDim  = dim3(128, 1, 1);
    cfg.blockDim = dim3(512, 1, 1);
    cudaLaunchAttribute attrs[1];
    attrs[0].id = cudaLaunchAttributeProgrammaticStreamSerialization;
    attrs[0].val.programmaticStreamSerializationAllowed = 1;
    cfg.attrs = attrs;
    cfg.numAttrs = 1;
    cudaLaunchKernelEx(&cfg, net_kernel, x, cidx, b_in, gat_b, emb, b_fuse,
                       b_p1, b_d1, b_p2, b_d2, W_p3, b_p3, W_d3, b_d3,
                       (float*)d_out);
}